// round 1
// baseline (speedup 1.0000x reference)
#include <cuda_runtime.h>
#include <cuda_bf16.h>
#include <cstdint>

#define N_NODES 50000
#define N_EDGES 800000
#define N_GRAPHS 128
#define D 128
#define L 4
#define C 10
#define GN_EPS 1e-5f

// ------------------------- device scratch (static, no allocs) -------------
__device__ float g_h[(size_t)N_NODES * D];
__device__ float g_a[(size_t)N_NODES * D];
__device__ float g_b[(size_t)N_NODES * D];
__device__ int   g_rowptr[N_NODES + 1];
__device__ int   g_cursor[N_NODES];
__device__ int   g_cnt[N_NODES];
__device__ int   g_col[N_EDGES];
__device__ int   g_gptr[N_GRAPHS + 1];
__device__ float g_gcnt[N_GRAPHS];
__device__ float g_pool[N_GRAPHS * D];
__device__ int   g_is64e;
__device__ int   g_is64b;

// ------------------------- index fetch (int32 / int64 agnostic) ----------
__device__ __forceinline__ int e_at(const void* p, long long i) {
    if (g_is64e) return (int)((const long long*)p)[i];
    return ((const int*)p)[i];
}
__device__ __forceinline__ int b_at(const void* p, long long i) {
    if (g_is64b) return (int)((const long long*)p)[i];
    return ((const int*)p)[i];
}

// ------------------------- dtype detection --------------------------------
__global__ void k_detect(const int* __restrict__ ew, const int* __restrict__ bw) {
    __shared__ int s_ez, s_bg;
    if (threadIdx.x == 0) { s_ez = 1; s_bg = 0; }
    __syncthreads();
    // edge_index: if int64, odd 32-bit words (high halves) are all 0.
    for (int i = threadIdx.x; i < 128; i += blockDim.x)
        if (ew[2 * i + 1] != 0) atomicAnd(&s_ez, 0);
    // batch is sorted ascending. If int32, the 32-bit word stream is
    // nondecreasing. If int64, word[2i]=value, word[2i+1]=0, so once the
    // value exceeds 0 we observe word[2i] > word[2i+1].
    for (int i = threadIdx.x; i < 24999; i += blockDim.x)
        if (bw[2 * i] > bw[2 * i + 1]) atomicOr(&s_bg, 1);
    __syncthreads();
    if (threadIdx.x == 0) { g_is64e = s_ez; g_is64b = s_bg; }
}

// ------------------------- CSR build ---------------------------------------
__global__ void k_zero_cnt() {
    int i = blockIdx.x * blockDim.x + threadIdx.x;
    if (i < N_NODES) g_cnt[i] = 0;
}

__global__ void k_hist(const void* __restrict__ e) {
    int i = blockIdx.x * blockDim.x + threadIdx.x;
    if (i < N_EDGES) {
        int d = e_at(e, (long long)N_EDGES + i);
        atomicAdd(&g_cnt[d], 1);
    }
}

__global__ void k_scan() {
    __shared__ int part[1024];
    int t = threadIdx.x;
    const int CH = (N_NODES + 1023) / 1024;  // 49
    int base = t * CH;
    int s = 0;
    for (int i = 0; i < CH; i++) {
        int idx = base + i;
        if (idx < N_NODES) s += g_cnt[idx];
    }
    part[t] = s;
    __syncthreads();
    for (int off = 1; off < 1024; off <<= 1) {
        int v = (t >= off) ? part[t - off] : 0;
        __syncthreads();
        part[t] += v;
        __syncthreads();
    }
    int run = (t == 0) ? 0 : part[t - 1];
    for (int i = 0; i < CH; i++) {
        int idx = base + i;
        if (idx < N_NODES) {
            g_rowptr[idx] = run;
            g_cursor[idx] = run;
            run += g_cnt[idx];
        }
    }
    if (t == 1023) g_rowptr[N_NODES] = part[1023];
}

__global__ void k_fill(const void* __restrict__ e) {
    int i = blockIdx.x * blockDim.x + threadIdx.x;
    if (i < N_EDGES) {
        int s = e_at(e, i);
        int d = e_at(e, (long long)N_EDGES + i);
        int pos = atomicAdd(&g_cursor[d], 1);
        g_col[pos] = s;
    }
}

// ------------------------- graph ranges ------------------------------------
__global__ void k_gptr(const void* __restrict__ batch) {
    __shared__ int cnt[N_GRAPHS];
    int t = threadIdx.x;
    cnt[t] = 0;
    __syncthreads();
    for (int n = t; n < N_NODES; n += N_GRAPHS) {
        int g = b_at(batch, n);
        atomicAdd(&cnt[g], 1);
    }
    __syncthreads();
    if (t == 0) {
        int run = 0;
        for (int g = 0; g < N_GRAPHS; g++) { g_gptr[g] = run; run += cnt[g]; }
        g_gptr[N_GRAPHS] = run;
    }
    g_gcnt[t] = fmaxf((float)cnt[t], 1.0f);
}

// ------------------------- aggregation: out = in + sum_{j->i} in[j] -------
__global__ void __launch_bounds__(256) k_agg(const float* __restrict__ in,
                                             float* __restrict__ out) {
    int warp = (blockIdx.x * blockDim.x + threadIdx.x) >> 5;
    int lane = threadIdx.x & 31;
    if (warp >= N_NODES) return;
    int s = g_rowptr[warp], e = g_rowptr[warp + 1];
    float4 acc = ((const float4*)(in + (size_t)warp * D))[lane];
    for (int i = s; i < e; i++) {
        int src = g_col[i];
        float4 v = __ldg(((const float4*)(in + (size_t)src * D)) + lane);
        acc.x += v.x; acc.y += v.y; acc.z += v.z; acc.w += v.w;
    }
    ((float4*)(out + (size_t)warp * D))[lane] = acc;
}

// ------------------------- fp32 tiled GEMM: C = relu(A @ W + b) -----------
#define BM 128
#define BN 128
#define BK 16
#define TM 8
#define TN 8

__global__ void __launch_bounds__(256) k_gemm(const float* __restrict__ A,
                                              const float* __restrict__ W,
                                              const float* __restrict__ bias,
                                              float* __restrict__ Cout) {
    __shared__ float As[BK][BM];
    __shared__ float Ws[BK][BN];
    int tid = threadIdx.x;
    int tx = tid & 15, ty = tid >> 4;
    int rowBase = blockIdx.x * BM;

    float acc[TM][TN];
#pragma unroll
    for (int i = 0; i < TM; i++)
#pragma unroll
        for (int j = 0; j < TN; j++) acc[i][j] = 0.f;

    for (int kk = 0; kk < D; kk += BK) {
#pragma unroll
        for (int it = 0; it < 2; it++) {      // A tile 128x16 -> As[k][m]
            int li = tid * 2 + it;            // 0..511
            int r  = li >> 2;                 // 0..127
            int c4 = li & 3;                  // 0..3
            float4 v = make_float4(0.f, 0.f, 0.f, 0.f);
            int gr = rowBase + r;
            if (gr < N_NODES)
                v = *(const float4*)(A + (size_t)gr * D + kk + c4 * 4);
            As[c4 * 4 + 0][r] = v.x;
            As[c4 * 4 + 1][r] = v.y;
            As[c4 * 4 + 2][r] = v.z;
            As[c4 * 4 + 3][r] = v.w;
        }
#pragma unroll
        for (int it = 0; it < 2; it++) {      // W tile 16x128 -> Ws[k][n]
            int li = tid * 2 + it;
            int r  = li >> 5;                 // 0..15
            int c4 = li & 31;                 // 0..31
            float4 v = *(const float4*)(W + (size_t)(kk + r) * D + c4 * 4);
            *(float4*)&Ws[r][c4 * 4] = v;
        }
        __syncthreads();
#pragma unroll
        for (int k = 0; k < BK; k++) {
            float a[TM], b[TN];
#pragma unroll
            for (int i = 0; i < TM; i++) a[i] = As[k][ty * TM + i];
#pragma unroll
            for (int j = 0; j < TN; j++) b[j] = Ws[k][tx * TN + j];
#pragma unroll
            for (int i = 0; i < TM; i++)
#pragma unroll
                for (int j = 0; j < TN; j++) acc[i][j] += a[i] * b[j];
        }
        __syncthreads();
    }

#pragma unroll
    for (int i = 0; i < TM; i++) {
        int gr = rowBase + ty * TM + i;
        if (gr >= N_NODES) continue;
#pragma unroll
        for (int j = 0; j < TN; j += 4) {
            int gc = tx * TN + j;
            float4 r;
            r.x = fmaxf(acc[i][j + 0] + bias[gc + 0], 0.f);
            r.y = fmaxf(acc[i][j + 1] + bias[gc + 1], 0.f);
            r.z = fmaxf(acc[i][j + 2] + bias[gc + 2], 0.f);
            r.w = fmaxf(acc[i][j + 3] + bias[gc + 3], 0.f);
            *(float4*)(Cout + (size_t)gr * D + gc) = r;
        }
    }
}

// ------------------------- GraphNorm + relu (in place on g_h) -------------
// Stats are per-(graph,dim) => thread d of block g is fully independent: no
// cross-thread reductions, three coalesced streaming passes, all L2-hot.
__global__ void __launch_bounds__(128) k_gnorm(const float* __restrict__ w,
                                               const float* __restrict__ b,
                                               const float* __restrict__ ms,
                                               int layer) {
    int g = blockIdx.x, d = threadIdx.x;
    int s = g_gptr[g], e = g_gptr[g + 1];
    float c = g_gcnt[g];
    float sum = 0.f;
    for (int n = s; n < e; n++) sum += g_h[(size_t)n * D + d];
    float meansc = (sum / c) * ms[layer * D + d];
    float ssq = 0.f;
    for (int n = s; n < e; n++) {
        float o = g_h[(size_t)n * D + d] - meansc;
        ssq += o * o;
    }
    float rstd = rsqrtf(ssq / c + GN_EPS);
    float ww = w[layer * D + d], bb = b[layer * D + d];
    for (int n = s; n < e; n++) {
        float o = g_h[(size_t)n * D + d] - meansc;
        g_h[(size_t)n * D + d] = fmaxf(ww * o * rstd + bb, 0.f);
    }
}

// ------------------------- sum-pool per graph ------------------------------
__global__ void __launch_bounds__(128) k_pool() {
    int g = blockIdx.x, d = threadIdx.x;
    int s = g_gptr[g], e = g_gptr[g + 1];
    float sum = 0.f;
    for (int n = s; n < e; n++) sum += g_h[(size_t)n * D + d];
    g_pool[g * D + d] = sum;
}

// ------------------------- final MLP + log_softmax -------------------------
__global__ void __launch_bounds__(128) k_mlp(const float* __restrict__ fw1,
                                             const float* __restrict__ fb1,
                                             const float* __restrict__ fw2,
                                             const float* __restrict__ fb2,
                                             const float* __restrict__ fw3,
                                             const float* __restrict__ fb3,
                                             float* __restrict__ out) {
    int g = blockIdx.x, t = threadIdx.x;
    __shared__ float v[D], v2[D], o[C], red[2];
    v[t] = g_pool[g * D + t];
    __syncthreads();
    float acc = fb1[t];
    for (int k = 0; k < D; k++) acc += v[k] * fw1[k * D + t];
    v2[t] = fmaxf(acc, 0.f);
    __syncthreads();
    acc = fb2[t];
    for (int k = 0; k < D; k++) acc += v2[k] * fw2[k * D + t];
    __syncthreads();        // all reads of v done before overwrite
    v[t] = fmaxf(acc, 0.f);
    __syncthreads();
    if (t < C) {
        float a = fb3[t];
        for (int k = 0; k < D; k++) a += v[k] * fw3[k * C + t];
        o[t] = a;
    }
    __syncthreads();
    if (t == 0) {
        float m = -1e30f;
        for (int c = 0; c < C; c++) m = fmaxf(m, o[c]);
        float se = 0.f;
        for (int c = 0; c < C; c++) se += expf(o[c] - m);
        red[0] = m;
        red[1] = logf(se);
    }
    __syncthreads();
    if (t < C) out[g * C + t] = o[t] - red[0] - red[1];
}

// ------------------------- launcher ----------------------------------------
extern "C" void kernel_launch(void* const* d_in, const int* in_sizes, int n_in,
                              void* d_out, int out_size) {
    const float* x    = (const float*)d_in[0];
    const float* w1   = (const float*)d_in[1];
    const float* b1   = (const float*)d_in[2];
    const float* w2   = (const float*)d_in[3];
    const float* b2   = (const float*)d_in[4];
    const float* gnw  = (const float*)d_in[5];
    const float* gnb  = (const float*)d_in[6];
    const float* gns  = (const float*)d_in[7];
    const float* fw1  = (const float*)d_in[8];
    const float* fb1  = (const float*)d_in[9];
    const float* fw2  = (const float*)d_in[10];
    const float* fb2  = (const float*)d_in[11];
    const float* fw3  = (const float*)d_in[12];
    const float* fb3  = (const float*)d_in[13];
    const void*  edge  = d_in[14];
    const void*  batch = d_in[15];
    float* out = (float*)d_out;

    // Device addresses of the static scratch buffers (query only, no alloc).
    float *p_h, *p_a, *p_b;
    cudaGetSymbolAddress((void**)&p_h, g_h);
    cudaGetSymbolAddress((void**)&p_a, g_a);
    cudaGetSymbolAddress((void**)&p_b, g_b);

    // dtype detection + CSR-by-dst + graph ranges (recomputed every call:
    // deterministic, allocation-free, ~1.6M int atomics total).
    k_detect<<<1, 256>>>((const int*)edge, (const int*)batch);
    k_zero_cnt<<<(N_NODES + 255) / 256, 256>>>();
    k_hist<<<(N_EDGES + 255) / 256, 256>>>(edge);
    k_scan<<<1, 1024>>>();
    k_fill<<<(N_EDGES + 255) / 256, 256>>>(edge);
    k_gptr<<<1, N_GRAPHS>>>(batch);

    const int gemmGrid = (N_NODES + BM - 1) / BM;     // 391
    const int aggGrid  = (N_NODES * 32 + 255) / 256;  // 6250

    for (int l = 0; l < L; l++) {
        const float* hin = (l == 0) ? x : p_h;
        k_agg<<<aggGrid, 256>>>(hin, p_a);
        k_gemm<<<gemmGrid, 256>>>(p_a, w1 + (size_t)l * D * D, b1 + (size_t)l * D, p_b);
        k_gemm<<<gemmGrid, 256>>>(p_b, w2 + (size_t)l * D * D, b2 + (size_t)l * D, p_h);
        k_gnorm<<<N_GRAPHS, D>>>(gnw, gnb, gns, l);
    }
    k_pool<<<N_GRAPHS, D>>>();
    k_mlp<<<N_GRAPHS, D>>>(fw1, fb1, fw2, fb2, fw3, fb3, out);
}

// round 3
// speedup vs baseline: 1.3043x; 1.3043x over previous
#include <cuda_runtime.h>
#include <cuda_bf16.h>
#include <cstdint>

#define N_NODES 50000
#define N_EDGES 800000
#define N_GRAPHS 128
#define D 128
#define L 4
#define C 10
#define GN_EPS 1e-5f
#define NB_SCAN 196
#define PAD 132

// ------------------------- device scratch (static, no allocs) -------------
__device__ float g_h[(size_t)N_NODES * D];
__device__ float g_a[(size_t)N_NODES * D];
__device__ float g_b[(size_t)N_NODES * D];
__device__ int   g_rowptr[N_NODES + 1];
__device__ int   g_cursor[N_NODES];
__device__ int   g_cnt[N_NODES];
__device__ int   g_col[N_EDGES];
__device__ int   g_bsum[NB_SCAN];
__device__ int   g_boff[NB_SCAN];
__device__ int   g_gptr[N_GRAPHS + 1];
__device__ int   g_gcnt_i[N_GRAPHS];
__device__ float g_gcnt[N_GRAPHS];
__device__ float g_pool[N_GRAPHS * D];
__device__ float g_stat[L][N_GRAPHS][2][D];     // [l][g][{sum,sumsq}][d]
__device__ float g_wT[8][16384];                // W^T (tf32-rounded), B[n][k]
__device__ int   g_is64e;
__device__ int   g_is64b;

// ------------------------- helpers ----------------------------------------
__device__ __forceinline__ int e_at(const void* p, long long i) {
    if (g_is64e) return (int)((const long long*)p)[i];
    return ((const int*)p)[i];
}
__device__ __forceinline__ int b_at(const void* p, long long i) {
    if (g_is64b) return (int)((const long long*)p)[i];
    return ((const int*)p)[i];
}
__device__ __forceinline__ float to_tf32(float x) {
    float r; asm("cvt.rna.tf32.f32 %0, %1;" : "=f"(r) : "f"(x)); return r;
}

// mma.sync m16n8k8 tf32: D = A*B + D
__device__ __forceinline__ void mma_tf32(float c[4], const float a[4],
                                         uint32_t b0, uint32_t b1) {
    const uint32_t* A = reinterpret_cast<const uint32_t*>(a);
    asm volatile(
        "mma.sync.aligned.m16n8k8.row.col.f32.tf32.tf32.f32 "
        "{%0,%1,%2,%3}, {%4,%5,%6,%7}, {%8,%9}, {%0,%1,%2,%3};"
        : "+f"(c[0]), "+f"(c[1]), "+f"(c[2]), "+f"(c[3])
        : "r"(A[0]), "r"(A[1]), "r"(A[2]), "r"(A[3]), "r"(b0), "r"(b1));
}

// ------------------------- dtype detection --------------------------------
__global__ void k_detect(const int* __restrict__ ew, const int* __restrict__ bw) {
    __shared__ int s_ez, s_bg;
    if (threadIdx.x == 0) { s_ez = 1; s_bg = 0; }
    if (threadIdx.x < N_GRAPHS) g_gcnt_i[threadIdx.x] = 0;
    __syncthreads();
    for (int i = threadIdx.x; i < 128; i += blockDim.x)
        if (ew[2 * i + 1] != 0) atomicAnd(&s_ez, 0);
    for (int i = threadIdx.x; i < 24999; i += blockDim.x)
        if (bw[2 * i] > bw[2 * i + 1]) atomicOr(&s_bg, 1);
    __syncthreads();
    if (threadIdx.x == 0) { g_is64e = s_ez; g_is64b = s_bg; }
}

// ------------------------- weight transpose (tf32-rounded) -----------------
__global__ void k_wt(const float* __restrict__ w1, const float* __restrict__ w2) {
    int m = blockIdx.x;                     // 0..7
    const float* W = (m < 4) ? (w1 + (size_t)m * D * D) : (w2 + (size_t)(m - 4) * D * D);
    for (int idx = threadIdx.x; idx < D * D; idx += blockDim.x) {
        int k = idx >> 7, n = idx & 127;
        g_wT[m][n * D + k] = to_tf32(W[idx]);   // B[n][k] = W[k][n]
    }
}

// ------------------------- CSR build ---------------------------------------
__global__ void k_zero_cnt() {
    int i = blockIdx.x * blockDim.x + threadIdx.x;
    if (i < N_NODES) g_cnt[i] = 0;
}
__global__ void k_zero_stat() {
    int i = blockIdx.x * blockDim.x + threadIdx.x;
    float* p = &g_stat[0][0][0][0];
    if (i < L * N_GRAPHS * 2 * D) p[i] = 0.f;
}
__global__ void k_hist(const void* __restrict__ e) {
    int i = blockIdx.x * blockDim.x + threadIdx.x;
    if (i < N_EDGES) atomicAdd(&g_cnt[e_at(e, (long long)N_EDGES + i)], 1);
}
__global__ void k_scan1() {
    __shared__ int sm[256];
    int t = threadIdx.x, idx = blockIdx.x * 256 + t;
    int v = (idx < N_NODES) ? g_cnt[idx] : 0;
    sm[t] = v; __syncthreads();
    for (int off = 1; off < 256; off <<= 1) {
        int u = (t >= off) ? sm[t - off] : 0;
        __syncthreads(); sm[t] += u; __syncthreads();
    }
    if (idx < N_NODES) g_cnt[idx] = sm[t] - v;   // local exclusive, in place
    if (t == 255) g_bsum[blockIdx.x] = sm[255];
}
__global__ void k_scan2() {
    __shared__ int sm[256];
    int t = threadIdx.x;
    int v = (t < NB_SCAN) ? g_bsum[t] : 0;
    sm[t] = v; __syncthreads();
    for (int off = 1; off < 256; off <<= 1) {
        int u = (t >= off) ? sm[t - off] : 0;
        __syncthreads(); sm[t] += u; __syncthreads();
    }
    if (t < NB_SCAN) g_boff[t] = sm[t] - v;
    if (t == NB_SCAN - 1) g_rowptr[N_NODES] = sm[t];
}
__global__ void k_scan3() {
    int idx = blockIdx.x * 256 + threadIdx.x;
    if (idx < N_NODES) {
        int rp = g_boff[blockIdx.x] + g_cnt[idx];
        g_rowptr[idx] = rp; g_cursor[idx] = rp;
    }
}
__global__ void k_fill(const void* __restrict__ e) {
    int i = blockIdx.x * blockDim.x + threadIdx.x;
    if (i < N_EDGES) {
        int s = e_at(e, i);
        int d = e_at(e, (long long)N_EDGES + i);
        g_col[atomicAdd(&g_cursor[d], 1)] = s;
    }
}
__global__ void k_ghist(const void* __restrict__ batch) {
    __shared__ int h[N_GRAPHS];
    int t = threadIdx.x;
    if (t < N_GRAPHS) h[t] = 0;
    __syncthreads();
    for (int n = blockIdx.x * blockDim.x + t; n < N_NODES; n += gridDim.x * blockDim.x)
        atomicAdd(&h[b_at(batch, n)], 1);
    __syncthreads();
    if (t < N_GRAPHS) atomicAdd(&g_gcnt_i[t], h[t]);
}
__global__ void k_gscan() {
    if (threadIdx.x == 0) {
        int run = 0;
        for (int g = 0; g < N_GRAPHS; g++) {
            g_gptr[g] = run;
            int c = g_gcnt_i[g];
            g_gcnt[g] = fmaxf((float)c, 1.0f);
            run += c;
        }
        g_gptr[N_GRAPHS] = run;
    }
}

// ------------------------- aggregation: out = in + sum_{j->i} in[j] -------
__global__ void __launch_bounds__(256) k_agg(const float* __restrict__ in,
                                             float* __restrict__ out) {
    int warp = (blockIdx.x * blockDim.x + threadIdx.x) >> 5;
    int lane = threadIdx.x & 31;
    if (warp >= N_NODES) return;
    int s = g_rowptr[warp], e = g_rowptr[warp + 1];
    float4 acc = ((const float4*)(in + (size_t)warp * D))[lane];
    for (int i = s; i < e; i++) {
        int src = g_col[i];
        float4 v = __ldg(((const float4*)(in + (size_t)src * D)) + lane);
        acc.x += v.x; acc.y += v.y; acc.z += v.z; acc.w += v.w;
    }
    ((float4*)(out + (size_t)warp * D))[lane] = acc;
}

// ------------------------- tf32 mma.sync GEMM: C = relu(A @ W + b) --------
// 256 thr = 8 warps, warp grid 4(m) x 2(n); warp tile 32x64; K=128 staged.
#define SMEM_GEMM (2 * 128 * PAD * 4)

__global__ void __launch_bounds__(256) k_gemm_mma(const float* __restrict__ A,
                                                  int mat,
                                                  const float* __restrict__ bias,
                                                  float* __restrict__ Cout) {
    extern __shared__ float sm[];
    float* As = sm;                 // [128][PAD]
    float* Bs = sm + 128 * PAD;     // [128][PAD]  (B[n][k])
    int tid = threadIdx.x, wid = tid >> 5, lane = tid & 31;
    int warp_m = wid & 3, warp_n = wid >> 2;
    int gID = lane >> 2, tig = lane & 3;
    int rb = blockIdx.x * 128;

    // stage A (tf32-rounded) and B
#pragma unroll
    for (int it = 0; it < 16; it++) {
        int idx = tid + it * 256;          // 0..4095
        int r = idx >> 5, c4 = (idx & 31) * 4;
        float4 v = make_float4(0.f, 0.f, 0.f, 0.f);
        if (rb + r < N_NODES) {
            v = *(const float4*)(A + (size_t)(rb + r) * D + c4);
            v.x = to_tf32(v.x); v.y = to_tf32(v.y);
            v.z = to_tf32(v.z); v.w = to_tf32(v.w);
        }
        *(float4*)(As + r * PAD + c4) = v;
        float4 w = *(const float4*)(g_wT[mat] + idx * 4);
        *(float4*)(Bs + r * PAD + c4) = w;
    }
    __syncthreads();

    float c[2][8][4];
#pragma unroll
    for (int i = 0; i < 2; i++)
#pragma unroll
        for (int j = 0; j < 8; j++)
#pragma unroll
            for (int q = 0; q < 4; q++) c[i][j][q] = 0.f;

#pragma unroll 2
    for (int kk = 0; kk < 16; kk++) {
        int k0 = kk * 8;
        float a[2][4];
#pragma unroll
        for (int i = 0; i < 2; i++) {
            int row = warp_m * 32 + i * 16;
            a[i][0] = As[(row + gID) * PAD + k0 + tig];
            a[i][1] = As[(row + gID + 8) * PAD + k0 + tig];
            a[i][2] = As[(row + gID) * PAD + k0 + tig + 4];
            a[i][3] = As[(row + gID + 8) * PAD + k0 + tig + 4];
        }
#pragma unroll
        for (int j = 0; j < 8; j++) {
            int n = warp_n * 64 + j * 8 + gID;
            uint32_t b0 = __float_as_uint(Bs[n * PAD + k0 + tig]);
            uint32_t b1 = __float_as_uint(Bs[n * PAD + k0 + tig + 4]);
            mma_tf32(c[0][j], a[0], b0, b1);
            mma_tf32(c[1][j], a[1], b0, b1);
        }
    }

    // epilogue: bias + relu, float2 stores
#pragma unroll
    for (int i = 0; i < 2; i++) {
        int r0 = rb + warp_m * 32 + i * 16 + gID;
        int r1 = r0 + 8;
#pragma unroll
        for (int j = 0; j < 8; j++) {
            int cb = warp_n * 64 + j * 8 + 2 * tig;
            float bx = bias[cb], by = bias[cb + 1];
            if (r0 < N_NODES) {
                float2 o0;
                o0.x = fmaxf(c[i][j][0] + bx, 0.f);
                o0.y = fmaxf(c[i][j][1] + by, 0.f);
                *(float2*)(Cout + (size_t)r0 * D + cb) = o0;
            }
            if (r1 < N_NODES) {
                float2 o1;
                o1.x = fmaxf(c[i][j][2] + bx, 0.f);
                o1.y = fmaxf(c[i][j][3] + by, 0.f);
                *(float2*)(Cout + (size_t)r1 * D + cb) = o1;
            }
        }
    }
}

// ------------------------- GraphNorm stats (single pass, strip/block) ------
__global__ void __launch_bounds__(128) k_gnstat(const void* __restrict__ batch,
                                                int layer) {
    int r0 = blockIdx.x * 128;
    int r1 = min(r0 + 128, N_NODES);
    int d = threadIdx.x;
    int curg = b_at(batch, r0);
    float s = 0.f, q = 0.f;
    for (int r = r0; r < r1; r++) {
        int g = b_at(batch, r);
        if (g != curg) {
            atomicAdd(&g_stat[layer][curg][0][d], s);
            atomicAdd(&g_stat[layer][curg][1][d], q);
            s = 0.f; q = 0.f; curg = g;
        }
        float v = g_h[(size_t)r * D + d];
        s += v; q += v * v;
    }
    atomicAdd(&g_stat[layer][curg][0][d], s);
    atomicAdd(&g_stat[layer][curg][1][d], q);
}

// ------------------------- GraphNorm apply + relu (warp per row) -----------
__global__ void __launch_bounds__(256) k_gnapply(const void* __restrict__ batch,
                                                 const float* __restrict__ w,
                                                 const float* __restrict__ b,
                                                 const float* __restrict__ ms,
                                                 int layer) {
    int warp = (blockIdx.x * blockDim.x + threadIdx.x) >> 5;
    int lane = threadIdx.x & 31;
    if (warp >= N_NODES) return;
    int g = b_at(batch, warp);
    float c = g_gcnt[g];
    int d0 = lane * 4;
    float4 h  = ((const float4*)(g_h + (size_t)warp * D))[lane];
    float4 s4 = *(const float4*)&g_stat[layer][g][0][d0];
    float4 q4 = *(const float4*)&g_stat[layer][g][1][d0];
    float4 ms4 = *(const float4*)(ms + layer * D + d0);
    float4 w4  = *(const float4*)(w  + layer * D + d0);
    float4 b4  = *(const float4*)(b  + layer * D + d0);
    float4 o;
#define GN1(X) {                                                   \
    float mean = s4.X / c;                                         \
    float a = mean * ms4.X;                                        \
    float var = q4.X / c - 2.f * a * mean + a * a;                 \
    float rstd = rsqrtf(var + GN_EPS);                             \
    o.X = fmaxf(w4.X * (h.X - a) * rstd + b4.X, 0.f); }
    GN1(x) GN1(y) GN1(z) GN1(w)
#undef GN1
    ((float4*)(g_h + (size_t)warp * D))[lane] = o;
}

// ------------------------- sum-pool per graph ------------------------------
__global__ void __launch_bounds__(1024) k_pool() {
    __shared__ float sm[1024];
    int g = blockIdx.x, t = threadIdx.x;
    int d = t & 127, strip = t >> 7;
    int s = g_gptr[g], e = g_gptr[g + 1];
    float p = 0.f;
    for (int r = s + strip; r < e; r += 8) p += g_h[(size_t)r * D + d];
    sm[t] = p;
    __syncthreads();
    if (t < 128) {
        float acc = 0.f;
#pragma unroll
        for (int i = 0; i < 8; i++) acc += sm[i * 128 + t];
        g_pool[g * D + t] = acc;
    }
}

// ------------------------- final MLP + log_softmax -------------------------
__global__ void __launch_bounds__(128) k_mlp(const float* __restrict__ fw1,
                                             const float* __restrict__ fb1,
                                             const float* __restrict__ fw2,
                                             const float* __restrict__ fb2,
                                             const float* __restrict__ fw3,
                                             const float* __restrict__ fb3,
                                             float* __restrict__ out) {
    int g = blockIdx.x, t = threadIdx.x;
    __shared__ float v[D], v2[D], o[C], red[2];
    v[t] = g_pool[g * D + t];
    __syncthreads();
    float acc = fb1[t];
    for (int k = 0; k < D; k++) acc += v[k] * fw1[k * D + t];
    v2[t] = fmaxf(acc, 0.f);
    __syncthreads();
    acc = fb2[t];
    for (int k = 0; k < D; k++) acc += v2[k] * fw2[k * D + t];
    __syncthreads();
    v[t] = fmaxf(acc, 0.f);
    __syncthreads();
    if (t < C) {
        float a = fb3[t];
        for (int k = 0; k < D; k++) a += v[k] * fw3[k * C + t];
        o[t] = a;
    }
    __syncthreads();
    if (t == 0) {
        float m = -1e30f;
        for (int c = 0; c < C; c++) m = fmaxf(m, o[c]);
        float se = 0.f;
        for (int c = 0; c < C; c++) se += expf(o[c] - m);
        red[0] = m; red[1] = logf(se);
    }
    __syncthreads();
    if (t < C) out[g * C + t] = o[t] - red[0] - red[1];
}

// ------------------------- launcher ----------------------------------------
extern "C" void kernel_launch(void* const* d_in, const int* in_sizes, int n_in,
                              void* d_out, int out_size) {
    const float* x    = (const float*)d_in[0];
    const float* w1   = (const float*)d_in[1];
    const float* b1   = (const float*)d_in[2];
    const float* w2   = (const float*)d_in[3];
    const float* b2   = (const float*)d_in[4];
    const float* gnw  = (const float*)d_in[5];
    const float* gnb  = (const float*)d_in[6];
    const float* gns  = (const float*)d_in[7];
    const float* fw1  = (const float*)d_in[8];
    const float* fb1  = (const float*)d_in[9];
    const float* fw2  = (const float*)d_in[10];
    const float* fb2  = (const float*)d_in[11];
    const float* fw3  = (const float*)d_in[12];
    const float* fb3  = (const float*)d_in[13];
    const void*  edge  = d_in[14];
    const void*  batch = d_in[15];
    float* out = (float*)d_out;

    float *p_h, *p_a, *p_b;
    cudaGetSymbolAddress((void**)&p_h, g_h);
    cudaGetSymbolAddress((void**)&p_a, g_a);
    cudaGetSymbolAddress((void**)&p_b, g_b);
    cudaFuncSetAttribute(k_gemm_mma, cudaFuncAttributeMaxDynamicSharedMemorySize,
                         SMEM_GEMM);

    // prep: dtype detect, weight transpose, CSR, graph ranges, stat zero
    k_detect<<<1, 256>>>((const int*)edge, (const int*)batch);
    k_wt<<<8, 256>>>(w1, w2);
    k_zero_cnt<<<(N_NODES + 255) / 256, 256>>>();
    k_zero_stat<<<(L * N_GRAPHS * 2 * D + 255) / 256, 256>>>();
    k_hist<<<(N_EDGES + 255) / 256, 256>>>(edge);
    k_scan1<<<NB_SCAN, 256>>>();
    k_scan2<<<1, 256>>>();
    k_scan3<<<NB_SCAN, 256>>>();
    k_fill<<<(N_EDGES + 255) / 256, 256>>>(edge);
    k_ghist<<<64, 256>>>(batch);
    k_gscan<<<1, 32>>>();

    const int gemmGrid = (N_NODES + 127) / 128;       // 391
    const int aggGrid  = (N_NODES * 32 + 255) / 256;  // 6250
    const int gnsGrid  = (N_NODES + 127) / 128;       // 391

    for (int l = 0; l < L; l++) {
        const float* hin = (l == 0) ? x : p_h;
        k_agg<<<aggGrid, 256>>>(hin, p_a);
        k_gemm_mma<<<gemmGrid, 256, SMEM_GEMM>>>(p_a, l,     b1 + (size_t)l * D, p_b);
        k_gemm_mma<<<gemmGrid, 256, SMEM_GEMM>>>(p_b, 4 + l, b2 + (size_t)l * D, p_h);
        k_gnstat<<<gnsGrid, 128>>>(batch, l);
        k_gnapply<<<aggGrid, 256>>>(batch, gnw, gnb, gns, l);
    }
    k_pool<<<N_GRAPHS, 1024>>>();
    k_mlp<<<N_GRAPHS, 128>>>(fw1, fb1, fw2, fb2, fw3, fb3, out);
}

// round 5
// speedup vs baseline: 1.6726x; 1.2823x over previous
#include <cuda_runtime.h>
#include <cuda_bf16.h>
#include <cstdint>

#define N_NODES 50000
#define N_EDGES 800000
#define N_GRAPHS 128
#define D 128
#define L 4
#define C 10
#define GN_EPS 1e-5f
#define NB_SCAN 196
#define PAD 132
#define ZERO_ELEMS (L * N_GRAPHS * 2 * D)   // 131072, largest scratch to clear

// ------------------------- device scratch (static, no allocs) -------------
__device__ float g_h[(size_t)N_NODES * D];
__device__ float g_a[(size_t)N_NODES * D];
__device__ int   g_rowptr[N_NODES + 1];
__device__ int   g_cursor[N_NODES];
__device__ int   g_cnt[N_NODES];
__device__ int   g_col[N_EDGES];
__device__ int   g_bsum[NB_SCAN];
__device__ int   g_boff[NB_SCAN];
__device__ int   g_gptr[N_GRAPHS + 1];
__device__ int   g_gcnt_i[N_GRAPHS];
__device__ float g_gcnt[N_GRAPHS];
__device__ float g_pool[N_GRAPHS * D];
__device__ float g_stat[L][N_GRAPHS][2][D];     // [l][g][{sum,sumsq}][d]
__device__ float g_wT[8][16384];                // W^T (tf32-rounded), B[n][k]
__device__ int   g_is64e;
__device__ int   g_is64b;

// ------------------------- helpers ----------------------------------------
__device__ __forceinline__ int e_at(const void* p, long long i) {
    if (g_is64e) return (int)((const long long*)p)[i];
    return ((const int*)p)[i];
}
__device__ __forceinline__ int b_at(const void* p, long long i) {
    if (g_is64b) return (int)((const long long*)p)[i];
    return ((const int*)p)[i];
}
__device__ __forceinline__ float to_tf32(float x) {
    float r; asm("cvt.rna.tf32.f32 %0, %1;" : "=f"(r) : "f"(x)); return r;
}

// mma.sync m16n8k8 tf32: D = A*B + D
__device__ __forceinline__ void mma_tf32(float c[4], const float a[4],
                                         uint32_t b0, uint32_t b1) {
    const uint32_t* A = reinterpret_cast<const uint32_t*>(a);
    asm volatile(
        "mma.sync.aligned.m16n8k8.row.col.f32.tf32.tf32.f32 "
        "{%0,%1,%2,%3}, {%4,%5,%6,%7}, {%8,%9}, {%0,%1,%2,%3};"
        : "+f"(c[0]), "+f"(c[1]), "+f"(c[2]), "+f"(c[3])
        : "r"(A[0]), "r"(A[1]), "r"(A[2]), "r"(A[3]), "r"(b0), "r"(b1));
}

// ------------------------- dtype detection --------------------------------
__global__ void k_detect(const int* __restrict__ ew, const int* __restrict__ bw) {
    __shared__ int s_ez, s_bg;
    if (threadIdx.x == 0) { s_ez = 1; s_bg = 0; }
    if (threadIdx.x < N_GRAPHS) g_gcnt_i[threadIdx.x] = 0;
    __syncthreads();
    for (int i = threadIdx.x; i < 128; i += blockDim.x)
        if (ew[2 * i + 1] != 0) atomicAnd(&s_ez, 0);
    for (int i = threadIdx.x; i < 24999; i += blockDim.x)
        if (bw[2 * i] > bw[2 * i + 1]) atomicOr(&s_bg, 1);
    __syncthreads();
    if (threadIdx.x == 0) { g_is64e = s_ez; g_is64b = s_bg; }
}

// ------------------------- weight transpose (tf32-rounded) -----------------
__global__ void k_wt(const float* __restrict__ w1, const float* __restrict__ w2) {
    int m = blockIdx.x;                     // 0..7
    const float* W = (m < 4) ? (w1 + (size_t)m * D * D) : (w2 + (size_t)(m - 4) * D * D);
    for (int idx = threadIdx.x; idx < D * D; idx += blockDim.x) {
        int k = idx >> 7, n = idx & 127;
        g_wT[m][n * D + k] = to_tf32(W[idx]);   // B[n][k] = W[k][n]
    }
}

// ------------------------- zero scratch ------------------------------------
// ZERO_ELEMS (131072) >= N_NODES (50000) >= N_GRAPHS*D (16384): grid must
// cover ZERO_ELEMS, otherwise stats accumulate across graph replays.
__global__ void k_zero() {
    int i = blockIdx.x * blockDim.x + threadIdx.x;
    if (i < N_NODES) g_cnt[i] = 0;
    if (i < ZERO_ELEMS) (&g_stat[0][0][0][0])[i] = 0.f;
    if (i < N_GRAPHS * D) g_pool[i] = 0.f;
}

// ------------------------- CSR build ---------------------------------------
__global__ void k_hist(const void* __restrict__ e) {
    int i = blockIdx.x * blockDim.x + threadIdx.x;
    if (i < N_EDGES) atomicAdd(&g_cnt[e_at(e, (long long)N_EDGES + i)], 1);
}
__global__ void k_scan1() {
    __shared__ int sm[256];
    int t = threadIdx.x, idx = blockIdx.x * 256 + t;
    int v = (idx < N_NODES) ? g_cnt[idx] : 0;
    sm[t] = v; __syncthreads();
    for (int off = 1; off < 256; off <<= 1) {
        int u = (t >= off) ? sm[t - off] : 0;
        __syncthreads(); sm[t] += u; __syncthreads();
    }
    if (idx < N_NODES) g_cnt[idx] = sm[t] - v;
    if (t == 255) g_bsum[blockIdx.x] = sm[255];
}
__global__ void k_scan2() {
    __shared__ int sm[256];
    int t = threadIdx.x;
    int v = (t < NB_SCAN) ? g_bsum[t] : 0;
    sm[t] = v; __syncthreads();
    for (int off = 1; off < 256; off <<= 1) {
        int u = (t >= off) ? sm[t - off] : 0;
        __syncthreads(); sm[t] += u; __syncthreads();
    }
    if (t < NB_SCAN) g_boff[t] = sm[t] - v;
    if (t == NB_SCAN - 1) g_rowptr[N_NODES] = sm[t];
}
__global__ void k_scan3() {
    int idx = blockIdx.x * 256 + threadIdx.x;
    if (idx < N_NODES) {
        int rp = g_boff[blockIdx.x] + g_cnt[idx];
        g_rowptr[idx] = rp; g_cursor[idx] = rp;
    }
}
__global__ void k_fill(const void* __restrict__ e) {
    int i = blockIdx.x * blockDim.x + threadIdx.x;
    if (i < N_EDGES) {
        int s = e_at(e, i);
        int d = e_at(e, (long long)N_EDGES + i);
        g_col[atomicAdd(&g_cursor[d], 1)] = s;
    }
}
__global__ void k_ghist(const void* __restrict__ batch) {
    __shared__ int h[N_GRAPHS];
    int t = threadIdx.x;
    if (t < N_GRAPHS) h[t] = 0;
    __syncthreads();
    for (int n = blockIdx.x * blockDim.x + t; n < N_NODES; n += gridDim.x * blockDim.x)
        atomicAdd(&h[b_at(batch, n)], 1);
    __syncthreads();
    if (t < N_GRAPHS) atomicAdd(&g_gcnt_i[t], h[t]);
}
__global__ void k_gscan() {
    if (threadIdx.x == 0) {
        int run = 0;
        for (int g = 0; g < N_GRAPHS; g++) {
            g_gptr[g] = run;
            int c = g_gcnt_i[g];
            g_gcnt[g] = fmaxf((float)c, 1.0f);
            run += c;
        }
        g_gptr[N_GRAPHS] = run;
    }
}

// ------------------------- aggregation: out = in + sum_{j->i} in[j] -------
__global__ void __launch_bounds__(256) k_agg(const float* __restrict__ in,
                                             float* __restrict__ out) {
    int warp = (blockIdx.x * blockDim.x + threadIdx.x) >> 5;
    int lane = threadIdx.x & 31;
    if (warp >= N_NODES) return;
    int s = g_rowptr[warp], e = g_rowptr[warp + 1];
    float4 acc = ((const float4*)(in + (size_t)warp * D))[lane];
    int i = s;
    // 4-deep unrolled gather (independent loads -> MLP~4)
    for (; i + 4 <= e; i += 4) {
        int s0 = g_col[i], s1 = g_col[i + 1], s2 = g_col[i + 2], s3 = g_col[i + 3];
        float4 v0 = __ldg(((const float4*)(in + (size_t)s0 * D)) + lane);
        float4 v1 = __ldg(((const float4*)(in + (size_t)s1 * D)) + lane);
        float4 v2 = __ldg(((const float4*)(in + (size_t)s2 * D)) + lane);
        float4 v3 = __ldg(((const float4*)(in + (size_t)s3 * D)) + lane);
        acc.x += v0.x + v1.x + v2.x + v3.x;
        acc.y += v0.y + v1.y + v2.y + v3.y;
        acc.z += v0.z + v1.z + v2.z + v3.z;
        acc.w += v0.w + v1.w + v2.w + v3.w;
    }
    for (; i < e; i++) {
        float4 v = __ldg(((const float4*)(in + (size_t)g_col[i] * D)) + lane);
        acc.x += v.x; acc.y += v.y; acc.z += v.z; acc.w += v.w;
    }
    ((float4*)(out + (size_t)warp * D))[lane] = acc;
}

// ------------------------- fused GIN MLP (gemm1+relu+gemm2+relu+stats) ----
// 256 thr = 8 warps, warp grid 4(m) x 2(n); warp tile 32x64; K=128 staged.
#define SMEM_GIN (3 * 128 * PAD * 4)

__global__ void __launch_bounds__(256) k_gin(const float* __restrict__ A,
                                             int layer,
                                             const float* __restrict__ bias1,
                                             const float* __restrict__ bias2,
                                             const void* __restrict__ batch,
                                             float* __restrict__ Hout) {
    extern __shared__ float sm[];
    float* As  = sm;                  // [128][PAD]  A tile, then H1 tile
    float* Bs1 = sm + 128 * PAD;      // [128][PAD]  W1^T; later final-H staging
    float* Bs2 = sm + 2 * 128 * PAD;  // [128][PAD]  W2^T
    __shared__ float b1s[128], b2s[128];
    __shared__ int gids[128];

    int tid = threadIdx.x, wid = tid >> 5, lane = tid & 31;
    int warp_m = wid & 3, warp_n = wid >> 2;
    int gID = lane >> 2, tig = lane & 3;
    int rb = blockIdx.x * 128;
    int nvalid = min(128, N_NODES - rb);

    // stage A (tf32-rounded), W1^T, W2^T
#pragma unroll
    for (int it = 0; it < 16; it++) {
        int idx = tid + it * 256;          // 0..4095
        int r = idx >> 5, c4 = (idx & 31) * 4;
        float4 v = make_float4(0.f, 0.f, 0.f, 0.f);
        if (r < nvalid) {
            v = *(const float4*)(A + (size_t)(rb + r) * D + c4);
            v.x = to_tf32(v.x); v.y = to_tf32(v.y);
            v.z = to_tf32(v.z); v.w = to_tf32(v.w);
        }
        *(float4*)(As + r * PAD + c4) = v;
        *(float4*)(Bs1 + r * PAD + c4) = *(const float4*)(g_wT[layer] + idx * 4);
        *(float4*)(Bs2 + r * PAD + c4) = *(const float4*)(g_wT[4 + layer] + idx * 4);
    }
    if (tid < 128) {
        b1s[tid] = bias1[tid];
        gids[tid] = (tid < nvalid) ? b_at(batch, rb + tid) : 0;
    } else {
        b2s[tid - 128] = bias2[tid - 128];
    }
    __syncthreads();

    float c[2][8][4];
    float a[2][4];

    // ---------------- GEMM1: H1 = relu(A @ W1 + b1) ----------------
#pragma unroll
    for (int i = 0; i < 2; i++)
#pragma unroll
        for (int j = 0; j < 8; j++)
#pragma unroll
            for (int q = 0; q < 4; q++) c[i][j][q] = 0.f;

#pragma unroll 2
    for (int kk = 0; kk < 16; kk++) {
        int k0 = kk * 8;
#pragma unroll
        for (int i = 0; i < 2; i++) {
            int row = warp_m * 32 + i * 16;
            a[i][0] = As[(row + gID) * PAD + k0 + tig];
            a[i][1] = As[(row + gID + 8) * PAD + k0 + tig];
            a[i][2] = As[(row + gID) * PAD + k0 + tig + 4];
            a[i][3] = As[(row + gID + 8) * PAD + k0 + tig + 4];
        }
#pragma unroll
        for (int j = 0; j < 8; j++) {
            int n = warp_n * 64 + j * 8 + gID;
            uint32_t b0 = __float_as_uint(Bs1[n * PAD + k0 + tig]);
            uint32_t b1 = __float_as_uint(Bs1[n * PAD + k0 + tig + 4]);
            mma_tf32(c[0][j], a[0], b0, b1);
            mma_tf32(c[1][j], a[1], b0, b1);
        }
    }
    __syncthreads();   // all reads of As / Bs1 complete

    // write H1 (tf32-rounded) back into As
#pragma unroll
    for (int i = 0; i < 2; i++) {
        int r0 = warp_m * 32 + i * 16 + gID;
#pragma unroll
        for (int j = 0; j < 8; j++) {
            int cb = warp_n * 64 + j * 8 + 2 * tig;
            As[r0 * PAD + cb]       = to_tf32(fmaxf(c[i][j][0] + b1s[cb], 0.f));
            As[r0 * PAD + cb + 1]   = to_tf32(fmaxf(c[i][j][1] + b1s[cb + 1], 0.f));
            As[(r0 + 8) * PAD + cb]     = to_tf32(fmaxf(c[i][j][2] + b1s[cb], 0.f));
            As[(r0 + 8) * PAD + cb + 1] = to_tf32(fmaxf(c[i][j][3] + b1s[cb + 1], 0.f));
        }
    }
    __syncthreads();

    // ---------------- GEMM2: H = relu(H1 @ W2 + b2) ----------------
#pragma unroll
    for (int i = 0; i < 2; i++)
#pragma unroll
        for (int j = 0; j < 8; j++)
#pragma unroll
            for (int q = 0; q < 4; q++) c[i][j][q] = 0.f;

#pragma unroll 2
    for (int kk = 0; kk < 16; kk++) {
        int k0 = kk * 8;
#pragma unroll
        for (int i = 0; i < 2; i++) {
            int row = warp_m * 32 + i * 16;
            a[i][0] = As[(row + gID) * PAD + k0 + tig];
            a[i][1] = As[(row + gID + 8) * PAD + k0 + tig];
            a[i][2] = As[(row + gID) * PAD + k0 + tig + 4];
            a[i][3] = As[(row + gID + 8) * PAD + k0 + tig + 4];
        }
#pragma unroll
        for (int j = 0; j < 8; j++) {
            int n = warp_n * 64 + j * 8 + gID;
            uint32_t b0 = __float_as_uint(Bs2[n * PAD + k0 + tig]);
            uint32_t b1 = __float_as_uint(Bs2[n * PAD + k0 + tig + 4]);
            mma_tf32(c[0][j], a[0], b0, b1);
            mma_tf32(c[1][j], a[1], b0, b1);
        }
    }

    // epilogue: H -> global + smem (Bs1 reused as staging for stats)
    float* Hs = Bs1;
#pragma unroll
    for (int i = 0; i < 2; i++) {
        int lr0 = warp_m * 32 + i * 16 + gID;
        int lr1 = lr0 + 8;
#pragma unroll
        for (int j = 0; j < 8; j++) {
            int cb = warp_n * 64 + j * 8 + 2 * tig;
            float2 o0, o1;
            o0.x = fmaxf(c[i][j][0] + b2s[cb], 0.f);
            o0.y = fmaxf(c[i][j][1] + b2s[cb + 1], 0.f);
            o1.x = fmaxf(c[i][j][2] + b2s[cb], 0.f);
            o1.y = fmaxf(c[i][j][3] + b2s[cb + 1], 0.f);
            Hs[lr0 * PAD + cb] = o0.x;  Hs[lr0 * PAD + cb + 1] = o0.y;
            Hs[lr1 * PAD + cb] = o1.x;  Hs[lr1 * PAD + cb + 1] = o1.y;
            if (lr0 < nvalid) *(float2*)(Hout + (size_t)(rb + lr0) * D + cb) = o0;
            if (lr1 < nvalid) *(float2*)(Hout + (size_t)(rb + lr1) * D + cb) = o1;
        }
    }
    __syncthreads();

    // per-graph stats (sum, sumsq) from smem, 2 strips of 64 rows
    {
        int d = tid & 127, half = tid >> 7;
        int r0 = half * 64, r1 = min(r0 + 64, nvalid);
        if (r0 < nvalid) {
            int curg = gids[r0];
            float s = 0.f, q = 0.f;
            for (int r = r0; r < r1; r++) {
                int g = gids[r];
                if (g != curg) {
                    atomicAdd(&g_stat[layer][curg][0][d], s);
                    atomicAdd(&g_stat[layer][curg][1][d], q);
                    s = 0.f; q = 0.f; curg = g;
                }
                float v = Hs[r * PAD + d];
                s += v; q += v * v;
            }
            atomicAdd(&g_stat[layer][curg][0][d], s);
            atomicAdd(&g_stat[layer][curg][1][d], q);
        }
    }
}

// ------------------------- GraphNorm apply + relu (+pool on last) ----------
__global__ void __launch_bounds__(256) k_gnapply(const void* __restrict__ batch,
                                                 const float* __restrict__ w,
                                                 const float* __restrict__ b,
                                                 const float* __restrict__ ms,
                                                 int layer, int last) {
    int warp = (blockIdx.x * blockDim.x + threadIdx.x) >> 5;
    int lane = threadIdx.x & 31;
    if (warp >= N_NODES) return;
    int g = b_at(batch, warp);
    float c = g_gcnt[g];
    int d0 = lane * 4;
    float4 h  = ((const float4*)(g_h + (size_t)warp * D))[lane];
    float4 s4 = *(const float4*)&g_stat[layer][g][0][d0];
    float4 q4 = *(const float4*)&g_stat[layer][g][1][d0];
    float4 ms4 = *(const float4*)(ms + layer * D + d0);
    float4 w4  = *(const float4*)(w  + layer * D + d0);
    float4 b4  = *(const float4*)(b  + layer * D + d0);
    float4 o;
#define GN1(X) {                                                   \
    float mean = s4.X / c;                                         \
    float aa = mean * ms4.X;                                       \
    float var = q4.X / c - 2.f * aa * mean + aa * aa;              \
    float rstd = rsqrtf(var + GN_EPS);                             \
    o.X = fmaxf(w4.X * (h.X - aa) * rstd + b4.X, 0.f); }
    GN1(x) GN1(y) GN1(z) GN1(w)
#undef GN1
    if (last) {
        atomicAdd(&g_pool[g * D + d0 + 0], o.x);
        atomicAdd(&g_pool[g * D + d0 + 1], o.y);
        atomicAdd(&g_pool[g * D + d0 + 2], o.z);
        atomicAdd(&g_pool[g * D + d0 + 3], o.w);
    } else {
        ((float4*)(g_h + (size_t)warp * D))[lane] = o;
    }
}

// ------------------------- final MLP + log_softmax -------------------------
__global__ void __launch_bounds__(128) k_mlp(const float* __restrict__ fw1,
                                             const float* __restrict__ fb1,
                                             const float* __restrict__ fw2,
                                             const float* __restrict__ fb2,
                                             const float* __restrict__ fw3,
                                             const float* __restrict__ fb3,
                                             float* __restrict__ out) {
    int g = blockIdx.x, t = threadIdx.x;
    __shared__ float v[D], v2[D], o[C], red[2];
    v[t] = g_pool[g * D + t];
    __syncthreads();
    float acc = fb1[t];
    for (int k = 0; k < D; k++) acc += v[k] * fw1[k * D + t];
    v2[t] = fmaxf(acc, 0.f);
    __syncthreads();
    acc = fb2[t];
    for (int k = 0; k < D; k++) acc += v2[k] * fw2[k * D + t];
    __syncthreads();
    v[t] = fmaxf(acc, 0.f);
    __syncthreads();
    if (t < C) {
        float a = fb3[t];
        for (int k = 0; k < D; k++) a += v[k] * fw3[k * C + t];
        o[t] = a;
    }
    __syncthreads();
    if (t == 0) {
        float m = -1e30f;
        for (int c = 0; c < C; c++) m = fmaxf(m, o[c]);
        float se = 0.f;
        for (int c = 0; c < C; c++) se += expf(o[c] - m);
        red[0] = m; red[1] = logf(se);
    }
    __syncthreads();
    if (t < C) out[g * C + t] = o[t] - red[0] - red[1];
}

// ------------------------- launcher ----------------------------------------
extern "C" void kernel_launch(void* const* d_in, const int* in_sizes, int n_in,
                              void* d_out, int out_size) {
    const float* x    = (const float*)d_in[0];
    const float* w1   = (const float*)d_in[1];
    const float* b1   = (const float*)d_in[2];
    const float* w2   = (const float*)d_in[3];
    const float* b2   = (const float*)d_in[4];
    const float* gnw  = (const float*)d_in[5];
    const float* gnb  = (const float*)d_in[6];
    const float* gns  = (const float*)d_in[7];
    const float* fw1  = (const float*)d_in[8];
    const float* fb1  = (const float*)d_in[9];
    const float* fw2  = (const float*)d_in[10];
    const float* fb2  = (const float*)d_in[11];
    const float* fw3  = (const float*)d_in[12];
    const float* fb3  = (const float*)d_in[13];
    const void*  edge  = d_in[14];
    const void*  batch = d_in[15];
    float* out = (float*)d_out;

    float *p_h, *p_a;
    cudaGetSymbolAddress((void**)&p_h, g_h);
    cudaGetSymbolAddress((void**)&p_a, g_a);
    cudaFuncSetAttribute(k_gin, cudaFuncAttributeMaxDynamicSharedMemorySize,
                         SMEM_GIN);

    // prologue: dtype detect, weight transpose, zero, CSR, graph ranges
    k_detect<<<1, 256>>>((const int*)edge, (const int*)batch);
    k_wt<<<8, 256>>>(w1, w2);
    k_zero<<<(ZERO_ELEMS + 255) / 256, 256>>>();   // 512 blocks: covers g_stat!
    k_hist<<<(N_EDGES + 255) / 256, 256>>>(edge);
    k_scan1<<<NB_SCAN, 256>>>();
    k_scan2<<<1, 256>>>();
    k_scan3<<<NB_SCAN, 256>>>();
    k_fill<<<(N_EDGES + 255) / 256, 256>>>(edge);
    k_ghist<<<64, 256>>>(batch);
    k_gscan<<<1, 32>>>();

    const int ginGrid = (N_NODES + 127) / 128;        // 391
    const int aggGrid = (N_NODES * 32 + 255) / 256;   // 6250

    for (int l = 0; l < L; l++) {
        const float* hin = (l == 0) ? x : p_h;
        k_agg<<<aggGrid, 256>>>(hin, p_a);
        k_gin<<<ginGrid, 256, SMEM_GIN>>>(p_a, l,
                                          b1 + (size_t)l * D, b2 + (size_t)l * D,
                                          batch, p_h);
        k_gnapply<<<aggGrid, 256>>>(batch, gnw, gnb, gns, l, l == L - 1);
    }
    k_mlp<<<N_GRAPHS, 128>>>(fw1, fb1, fw2, fb2, fw3, fb3, out);
}